// round 6
// baseline (speedup 1.0000x reference)
#include <cuda_runtime.h>
#include <math.h>

#define BATCH 8
#define NC 80
#define NA 8400
#define NA0 6400
#define NA1 1600
#define NA2 400
#define PRE_TOPK 5000
#define KMAX 100
#define TOTK (NC*KMAX)
#define SCORE_THR 0.01f
#define IOU_THR 0.65f
#define NTH 256
#define CAP2 3072     /* candidate pool capacity */
#define CAP 512       /* batch buffer */
#define BSEL 384      /* batch selection target */
#define FSORT 256
#define PFN 128
#define PADKEY 0xFFFFFFFFFFFFFFFFull
#define FULLM 0xFFFFFFFFu
typedef unsigned long long u64;

// ---------------- scratch ----------------
__device__ float g_kept_score[BATCH*TOTK];
__device__ float g_kept_box  [BATCH*TOTK*4];
__device__ int   g_done[BATCH];          // zero-initialized; self-resetting

// decision-exact IoU>thr test; IEEE div only in tiny ambiguity band
__device__ __forceinline__ bool iou_sup(float SX1,float SY1,float SX2,float SY2,float SAR,
                                        float x1,float y1,float x2,float y2,float ar){
    float tlx = fmaxf(SX1, x1), tly = fmaxf(SY1, y1);
    float brx = fminf(SX2, x2), bry = fminf(SY2, y2);
    float ww = fmaxf(brx - tlx, 0.f), hh = fmaxf(bry - tly, 0.f);
    float inter = ww*hh;
    float denom = SAR + ar - inter + 1e-6f;
    float d = inter - IOU_THR*denom;
    if (fabsf(d) > 1e-4f*denom) return d > 0.f;
    return __fdiv_rn(inter, denom) > IOU_THR;
}

// monotone cheap approx of 1+e^{-x} (selection surrogate only)
__device__ __forceinline__ float qapprox(float x){
    float t = fminf(fmaxf(-x, -80.f), 80.f);
    int bits = (int)(12102203.0f*t + 1064986316.0f);
    return 1.0f + __int_as_float(bits);
}

// warp-aggregated append
__device__ __forceinline__ void wappend(u64* buf, int* cnt, bool pred, u64 val, int bound){
    unsigned pm = __ballot_sync(FULLM, pred);
    if (!pm) return;
    int lane = (int)(threadIdx.x & 31);
    int ldr  = __ffs(pm) - 1;
    int base = 0;
    if (lane == ldr) base = atomicAdd(cnt, __popc(pm));
    base = __shfl_sync(FULLM, base, ldr);
    if (pred){
        int p = base + __popc(pm & ((1u<<lane)-1u));
        if (p < bound) buf[p] = val;
    }
}

// warp-0 collective bin scan with early whole-bin accept
__device__ __forceinline__ void scan_select(const unsigned* hist, int lane,
        unsigned prefix, int kk, int shift, int accCap,
        unsigned* s_pref, int* s_kkv, int* s_seldone, int* s_total){
    unsigned cc[8]; unsigned sum = 0;
    #pragma unroll
    for (int j = 0; j < 8; j++){ cc[j] = hist[lane*8+j]; sum += cc[j]; }
    unsigned incl = sum;
    #pragma unroll
    for (int off = 1; off < 32; off <<= 1){
        unsigned n = __shfl_up_sync(FULLM, incl, off);
        if (lane >= off) incl += n;
    }
    unsigned excl = incl - sum;
    unsigned total = __shfl_sync(FULLM, incl, 31);
    if (s_total && lane == 0) *s_total = (int)total;
    if ((int)excl < kk && kk <= (int)incl){
        unsigned run = excl;
        #pragma unroll
        for (int j = 0; j < 8; j++){
            if (run + cc[j] >= (unsigned)kk){
                unsigned binv = ((unsigned)(lane*8+j)) << shift;
                if (shift == 0){ *s_pref = prefix | binv; *s_seldone = 1; }
                else if ((int)(run + cc[j]) <= accCap){
                    *s_pref = prefix | binv | ((1u<<shift)-1u); *s_seldone = 1;
                } else { *s_pref = prefix | binv; *s_kkv = kk - (int)run; }
                break;
            }
            run += cc[j];
        }
    }
}

// exact box decode (identical arithmetic to all passing rounds)
__device__ __forceinline__ float4 decode_box(int a, int b,
        const float* __restrict__ bb0, const float* __restrict__ bb1,
        const float* __restrict__ bb2){
    float p0,p1,p2,p3,px,py,st;
    if (a < NA0){ int hw=a; const float* p=bb0+(size_t)b*4*NA0;
        p0=p[hw];p1=p[NA0+hw];p2=p[2*NA0+hw];p3=p[3*NA0+hw];
        px=(float)(hw%80)*8.f; py=(float)(hw/80)*8.f; st=8.f;
    } else if (a < NA0+NA1){ int hw=a-NA0; const float* p=bb1+(size_t)b*4*NA1;
        p0=p[hw];p1=p[NA1+hw];p2=p[2*NA1+hw];p3=p[3*NA1+hw];
        px=(float)(hw%40)*16.f; py=(float)(hw/40)*16.f; st=16.f;
    } else { int hw=a-NA0-NA1; const float* p=bb2+(size_t)b*4*NA2;
        p0=p[hw];p1=p[NA2+hw];p2=p[2*NA2+hw];p3=p[3*NA2+hw];
        px=(float)(hw%20)*32.f; py=(float)(hw/20)*32.f; st=32.f;
    }
    float cx=p0*st+px, cy=p1*st+py, w=expf(p2)*st, h=expf(p3)*st;
    return make_float4(cx-w*0.5f, cy-h*0.5f, cx+w*0.5f, cy+h*0.5f);
}

__device__ __forceinline__ float cls_at(int a, const float* c0, const float* c1, const float* c2){
    if (a < NA0) return c0[a];
    if (a < NA0+NA1) return c1[a-NA0];
    return c2[a-NA0-NA1];
}
__device__ __forceinline__ float obj_at(int a, const float* o0, const float* o1, const float* o2){
    if (a < NA0) return o0[a];
    if (a < NA0+NA1) return o1[a-NA0];
    return o2[a-NA0-NA1];
}

// surrogate q-bits for quad i (i in [0,2100))
__device__ __forceinline__ void quad_qs(int i, unsigned q[4],
        const float4* c0v, const float4* c1v, const float4* c2v,
        const float4* o0v, const float4* o1v, const float4* o2v){
    float4 cv, ov;
    if (i < 1600){ cv = c0v[i];       ov = o0v[i]; }
    else if (i < 2000){ cv = c1v[i-1600]; ov = o1v[i-1600]; }
    else { cv = c2v[i-2000]; ov = o2v[i-2000]; }
    q[0] = __float_as_uint(qapprox(cv.x)*qapprox(ov.x));
    q[1] = __float_as_uint(qapprox(cv.y)*qapprox(ov.y));
    q[2] = __float_as_uint(qapprox(cv.z)*qapprox(ov.z));
    q[3] = __float_as_uint(qapprox(cv.w)*qapprox(ov.w));
}

// ---------------- the fused kernel ----------------
__global__ __launch_bounds__(NTH, 5) void k_all(
    const float* __restrict__ cls0, const float* __restrict__ bb0, const float* __restrict__ obj0,
    const float* __restrict__ cls1, const float* __restrict__ bb1, const float* __restrict__ obj1,
    const float* __restrict__ cls2, const float* __restrict__ bb2, const float* __restrict__ obj2,
    float* __restrict__ out){

    extern __shared__ char smraw[];
    u64* pool  = (u64*)smraw;                                   // CAP2
    u64* bk    = (u64*)(smraw + (size_t)CAP2*8);                // CAP
    float4* pbox = (float4*)(smraw + (size_t)CAP2*8 + (size_t)CAP*8); // PFN

    __shared__ float kx1[KMAX], ky1[KMAX], kx2[KMAX], ky2[KMAX], ksc[KMAX], kar[KMAX];
    __shared__ unsigned hist[256];
    __shared__ float cbx1[32], cby1[32], cbx2[32], cby2[32], cbar[32], cbs[32];
    __shared__ unsigned conf[32];
    __shared__ int sup[32];
    __shared__ unsigned s_pref, s_vmask;
    __shared__ int s_kkv, s_total, s_seldone, s_cnt, s_kept, s_rank, s_pool, s_last;
    __shared__ u64 fkey[FSORT];

    int tid = threadIdx.x;
    int lane = tid & 31, w = tid >> 5;
    int bc = blockIdx.x;
    int b = bc / NC, c = bc % NC;

    const float* c0 = cls0 + ((size_t)b*NC + c)*NA0;
    const float* c1 = cls1 + ((size_t)b*NC + c)*NA1;
    const float* c2 = cls2 + ((size_t)b*NC + c)*NA2;
    const float* o0 = obj0 + (size_t)b*NA0;
    const float* o1 = obj1 + (size_t)b*NA1;
    const float* o2 = obj2 + (size_t)b*NA2;
    const float4* c0v = (const float4*)c0;
    const float4* c1v = (const float4*)c1;
    const float4* c2v = (const float4*)c2;
    const float4* o0v = (const float4*)o0;
    const float4* o1v = (const float4*)o1;
    const float4* o2v = (const float4*)o2;

    const unsigned Q2BITS = __float_as_uint(2.35f);   // pool band: score_sur > ~0.43
    const unsigned QHI    = __float_as_uint(110.0f);  // score_sur > ~0.009 band

    if (tid == 0){ s_pool = 0; s_kept = 0; s_rank = 0; }
    __syncthreads();

    // ---- single streaming pass: append pool candidates ----
    {
        const int NQ = (2100 + NTH - 1)/NTH;
        for (int it = 0; it < NQ; it++){
            int i = it*NTH + tid;
            bool inb = i < 2100;
            unsigned q[4] = {0xFFFFFFFFu,0xFFFFFFFFu,0xFFFFFFFFu,0xFFFFFFFFu};
            if (inb) quad_qs(i, q, c0v,c1v,c2v, o0v,o1v,o2v);
            #pragma unroll
            for (int k = 0; k < 4; k++)
                wappend(pool, &s_pool, inb && q[k] < Q2BITS,
                        ((u64)q[k] << 32) | (unsigned)(4*i + k), CAP2);
        }
    }
    __syncthreads();
    int C2 = s_pool;
    bool gmode = (C2 > CAP2);      // pool overflow -> exact full-domain mode
    unsigned prevT = 0;
    bool done = false;
    const int NQ = (2100 + NTH - 1)/NTH;

    while (!done){
        // ---- pass-1 histogram ----
        hist[tid] = 0;
        if (tid == 0) s_seldone = 0;
        __syncthreads();
        if (!gmode){
            for (int p = tid; p < C2; p += NTH){
                unsigned v = (unsigned)(pool[p] >> 32);
                if (v > prevT) atomicAdd(&hist[v>>24], 1u);
            }
        } else {
            for (int it = 0; it < NQ; it++){
                int i = it*NTH + tid;
                bool inb = i < 2100;
                unsigned q[4] = {0xFFFFFFFFu,0xFFFFFFFFu,0xFFFFFFFFu,0xFFFFFFFFu};
                if (inb) quad_qs(i, q, c0v,c1v,c2v, o0v,o1v,o2v);
                #pragma unroll
                for (int k = 0; k < 4; k++)
                    if (inb && q[k] < QHI && q[k] > prevT) atomicAdd(&hist[q[k]>>24], 1u);
            }
        }
        __syncthreads();
        if (tid < 32)
            scan_select(hist, lane, 0u, BSEL, 24, CAP, &s_pref, &s_kkv, &s_seldone, &s_total);
        __syncthreads();
        int total = s_total;
        if (total == 0){
            if (!gmode){ gmode = true; prevT = Q2BITS - 1u; continue; }
            break;
        }
        bool takeall = (total <= CAP);
        unsigned T = 0xFFFFFFFFu;

        if (!takeall){
            for (int shift = 16; shift >= 0; shift -= 8){
                if (s_seldone) break;
                unsigned prefix = s_pref; int kk = s_kkv;
                unsigned mask = 0xFFFFFFFFu << (shift+8);
                hist[tid] = 0; __syncthreads();
                if (!gmode){
                    for (int p = tid; p < C2; p += NTH){
                        unsigned v = (unsigned)(pool[p] >> 32);
                        if (v > prevT && (v & mask) == prefix)
                            atomicAdd(&hist[(v>>shift)&255], 1u);
                    }
                } else {
                    for (int it = 0; it < NQ; it++){
                        int i = it*NTH + tid;
                        bool inb = i < 2100;
                        unsigned q[4] = {0xFFFFFFFFu,0xFFFFFFFFu,0xFFFFFFFFu,0xFFFFFFFFu};
                        if (inb) quad_qs(i, q, c0v,c1v,c2v, o0v,o1v,o2v);
                        #pragma unroll
                        for (int k = 0; k < 4; k++)
                            if (inb && q[k] < QHI && q[k] > prevT && (q[k] & mask) == prefix)
                                atomicAdd(&hist[(q[k]>>shift)&255], 1u);
                    }
                }
                __syncthreads();
                if (tid < 32)
                    scan_select(hist, lane, prefix, kk, shift, CAP - BSEL + kk,
                                &s_pref, &s_kkv, &s_seldone, 0);
                __syncthreads();
            }
            T = s_pref;
        }

        // ---- compact this batch's anchor indices ----
        if (tid == 0) s_cnt = 0;
        __syncthreads();
        if (!gmode){
            for (int p = tid; p < C2; p += NTH){
                u64 e = pool[p];
                unsigned v = (unsigned)(e >> 32);
                if (v > prevT && (takeall || v <= T)){
                    int q = atomicAdd(&s_cnt, 1);
                    if (q < CAP) bk[q] = e & 0xFFFFFFFFull;
                }
            }
        } else {
            for (int it = 0; it < NQ; it++){
                int i = it*NTH + tid;
                bool inb = i < 2100;
                unsigned q[4] = {0xFFFFFFFFu,0xFFFFFFFFu,0xFFFFFFFFu,0xFFFFFFFFu};
                if (inb) quad_qs(i, q, c0v,c1v,c2v, o0v,o1v,o2v);
                #pragma unroll
                for (int k = 0; k < 4; k++)
                    wappend(bk, &s_cnt,
                            inb && q[k] < QHI && q[k] > prevT && (takeall || q[k] <= T),
                            (u64)(unsigned)(4*i + k), CAP);
            }
        }
        __syncthreads();
        int cnt = min(s_cnt, CAP);
        int sortN = (cnt <= 256) ? 256 : 512;

        // ---- exact rescore (bit-identical to reference path) ----
        for (int p = tid; p < sortN; p += NTH){
            if (p < cnt){
                int a = (int)(unsigned)bk[p];
                float cv = cls_at(a, c0, c1, c2);
                float ov = obj_at(a, o0, o1, o2);
                float s = (1.0f/(1.0f+expf(-cv))) * (1.0f/(1.0f+expf(-ov)));
                bk[p] = (s > SCORE_THR)
                    ? (((u64)(~__float_as_uint(s)) << 32) | (unsigned)a)
                    : PADKEY;
            } else bk[p] = PADKEY;
        }
        __syncthreads();

        // ---- bitonic sort: score desc, ties lower index first ----
        for (int ksz = 2; ksz <= sortN; ksz <<= 1){
            for (int j = ksz >> 1; j > 0; j >>= 1){
                for (int idx = tid; idx < sortN; idx += NTH){
                    int l = idx ^ j;
                    if (l > idx){
                        u64 a0 = bk[idx], a1 = bk[l];
                        bool up = ((idx & ksz) == 0);
                        if ((a0 > a1) == up){ bk[idx] = a1; bk[l] = a0; }
                    }
                }
                __syncthreads();
            }
        }

        // ---- decode boxes for first PFN sorted candidates ----
        int pn = min(cnt, PFN);
        for (int p = tid; p < pn; p += NTH){
            u64 k2 = bk[p];
            if (k2 != PADKEY)
                pbox[p] = decode_box((int)(unsigned)(k2 & 0xFFFFFFFFull), b, bb0, bb1, bb2);
        }
        __syncthreads();

        // ---- greedy NMS over chunks of 32 sorted candidates ----
        int t0 = 0;
        while (t0 < cnt){
            int K = s_kept, rank = s_rank;
            if (K >= KMAX || rank >= PRE_TOPK) break;
            int chunk_n = min(32, min(cnt - t0, PRE_TOPK - rank));

            if (tid < 32){
                bool lv = lane < chunk_n;
                u64 k2 = lv ? bk[t0+lane] : PADKEY;
                bool cvalid = lv && (k2 != PADKEY);
                float4 bb = make_float4(0.f,0.f,0.f,0.f);
                float sval = 0.f;
                if (cvalid){
                    int t = t0 + lane;
                    int a = (int)(unsigned)(k2 & 0xFFFFFFFFull);
                    sval = __uint_as_float(~(unsigned)(k2>>32));
                    bb = (t < pn) ? pbox[t] : decode_box(a, b, bb0, bb1, bb2);
                }
                cbx1[lane]=bb.x; cby1[lane]=bb.y; cbx2[lane]=bb.z; cby2[lane]=bb.w;
                cbar[lane]=(bb.z-bb.x)*(bb.w-bb.y); cbs[lane]=sval;
                conf[lane]=0; sup[lane]=0;
                unsigned vm = __ballot_sync(FULLM, cvalid);
                if (lane == 0) s_vmask = vm;
            }
            __syncthreads();
            unsigned vm = s_vmask;

            {   // all 8 warps: kept-suppression + intra-chunk conflict matrix
                int i = lane;
                if ((vm>>i)&1u){
                    float x1=cbx1[i], y1=cby1[i], x2=cbx2[i], y2=cby2[i], ar=cbar[i];
                    bool s = false;
                    for (int m = w; m < K; m += 8)
                        s |= iou_sup(kx1[m],ky1[m],kx2[m],ky2[m],kar[m], x1,y1,x2,y2,ar);
                    if (s) sup[i] = 1;
                    unsigned cf = 0;
                    for (int j = w; j < i; j += 8){
                        if ((vm>>j)&1u){
                            if (iou_sup(cbx1[j],cby1[j],cbx2[j],cby2[j],cbar[j],
                                        x1,y1,x2,y2,ar)) cf |= 1u<<j;
                        }
                    }
                    if (cf) atomicOr(&conf[i], cf);
                }
            }
            __syncthreads();

            if (tid < 32){
                bool base_ok = ((vm>>lane)&1u) && (sup[lane] == 0);
                unsigned myconf = conf[lane];
                unsigned undecided = __ballot_sync(FULLM, base_ok);
                unsigned kept_mask = 0;
                while (undecided){
                    bool und = (undecided >> lane) & 1u;
                    bool decidable = und && ((myconf & undecided & ~(1u<<lane)) == 0);
                    bool keepme = decidable && ((myconf & kept_mask) == 0);
                    unsigned dec = __ballot_sync(FULLM, decidable);
                    unsigned kp  = __ballot_sync(FULLM, keepme);
                    kept_mask |= kp;
                    undecided &= ~dec;
                }
                int pos = K + __popc(kept_mask & ((1u<<lane)-1u));
                if (((kept_mask>>lane)&1u) && pos < KMAX){
                    kx1[pos]=cbx1[lane]; ky1[pos]=cby1[lane];
                    kx2[pos]=cbx2[lane]; ky2[pos]=cby2[lane];
                    kar[pos]=cbar[lane]; ksc[pos]=cbs[lane];
                }
                if (lane == 0){
                    s_kept = min(K + __popc(kept_mask), KMAX);
                    s_rank = rank + chunk_n;
                }
            }
            __syncthreads();
            t0 += 32;
        }

        if (s_kept >= KMAX || s_rank >= PRE_TOPK) done = true;
        else if (takeall){
            if (!gmode){ gmode = true; prevT = Q2BITS - 1u; }
            else done = true;
        } else prevT = T;
        __syncthreads();
    }

    // ---- per-class outputs ----
    int kept = s_kept;
    float* keptS = g_kept_score + (size_t)bc*KMAX;
    float* keptB = g_kept_box   + (size_t)bc*KMAX*4;
    for (int j = tid; j < KMAX; j += NTH){
        if (j < kept){
            keptS[j] = ksc[j];
            keptB[j*4+0]=kx1[j]; keptB[j*4+1]=ky1[j];
            keptB[j*4+2]=kx2[j]; keptB[j*4+3]=ky2[j];
        } else {
            keptS[j] = -1.f;
            keptB[j*4+0]=0.f; keptB[j*4+1]=0.f; keptB[j*4+2]=0.f; keptB[j*4+3]=0.f;
        }
    }

    // ---- last CTA of this image runs the global top-100 ----
    __threadfence();
    __syncthreads();
    if (tid == 0){
        int r = atomicAdd(&g_done[b], 1);
        s_last = (r == NC - 1) ? 1 : 0;
    }
    __syncthreads();
    if (!s_last) return;
    __threadfence();

    const float* ks = g_kept_score + (size_t)b*TOTK;
    const int NJ = (TOTK + NTH - 1)/NTH;

    // radix select: KMAX-th largest mapped value
    unsigned prefix = 0; int kk = KMAX;
    for (int shift = 24; shift >= 0; shift -= 8){
        unsigned mask = (shift == 24) ? 0u : (0xFFFFFFFFu << (shift+8));
        hist[tid] = 0; __syncthreads();
        for (int it = 0; it < NJ; it++){
            int j = it*NTH + tid;
            if (j < TOTK){
                unsigned u = __float_as_uint(ks[j]);
                unsigned v = (u & 0x80000000u) ? ~u : (u | 0x80000000u);
                // descending rank: count from top -> use inverted bins via suffix logic:
                if ((v & mask) == prefix) atomicAdd(&hist[(v>>shift)&255], 1u);
            }
        }
        __syncthreads();
        if (tid < 32){
            // suffix scan for descending select
            unsigned cc[8]; unsigned sum = 0;
            #pragma unroll
            for (int q = 0; q < 8; q++){ cc[q] = hist[lane*8+q]; sum += cc[q]; }
            // inclusive suffix sums across warp (reverse)
            unsigned incl = sum;
            #pragma unroll
            for (int off = 1; off < 32; off <<= 1){
                unsigned n = __shfl_down_sync(FULLM, incl, off);
                if (lane + off < 32) incl += n;
            }
            // incl = sum of bins [lane*8 .. 255]
            unsigned below = incl - sum;   // bins above lane's group (higher values)... careful: incl covers lane..31 groups
            if ((int)below < kk && kk <= (int)incl){
                unsigned run = below;
                for (int q = 7; q >= 0; q--){
                    if (run + cc[q] >= (unsigned)kk){
                        s_pref = prefix | (((unsigned)(lane*8+q)) << shift);
                        s_kkv  = kk - (int)run;
                        break;
                    }
                    run += cc[q];
                }
            }
        }
        __syncthreads();
        prefix = s_pref; kk = s_kkv;
        __syncthreads();
    }
    unsigned T = prefix;
    const unsigned MAP0 = 0x80000000u;

    if (tid == 0) s_cnt = 0;
    __syncthreads();
    for (int it = 0; it < NJ; it++){
        int j = it*NTH + tid;
        bool inb = j < TOTK;
        unsigned v = 0;
        if (inb){
            unsigned u = __float_as_uint(ks[j]);
            v = (u & 0x80000000u) ? ~u : (u | 0x80000000u);
        }
        wappend(fkey, &s_cnt, inb && v >= T && v > MAP0,
                ((u64)v << 32) | (0xFFFFFFFFu - (unsigned)j), FSORT);
    }
    __syncthreads();
    int fcnt = min(s_cnt, FSORT);
    for (int p = fcnt + tid; p < FSORT; p += NTH) fkey[p] = 0ull;
    __syncthreads();

    for (int ksz = 2; ksz <= FSORT; ksz <<= 1){
        for (int j = ksz >> 1; j > 0; j >>= 1){
            if (tid < FSORT){
                int idx = tid, l = idx ^ j;
                if (l > idx){
                    u64 a0 = fkey[idx], a1 = fkey[l];
                    bool up = ((idx & ksz) == 0);
                    if ((a0 > a1) == up){ fkey[idx] = a1; fkey[l] = a0; }
                }
            }
            __syncthreads();
        }
    }

    float* out_num = out;
    float* out_box = out + BATCH;
    float* out_sc  = out + BATCH + (size_t)BATCH*KMAX*4;
    float* out_cl  = out + BATCH + (size_t)BATCH*KMAX*4 + (size_t)BATCH*KMAX;

    for (int k = tid; k < KMAX; k += NTH){
        bool valid = (k < fcnt);
        float s = 0.f, cl = -1.f, b0=0.f, b1=0.f, b2=0.f, b3=0.f;
        if (valid){
            u64 k2 = fkey[FSORT-1-k];
            int flat = (int)(0xFFFFFFFFu - (unsigned)(k2 & 0xFFFFFFFFull));
            s  = g_kept_score[(size_t)b*TOTK + flat];
            cl = (float)(flat / KMAX);
            const float* bb = &g_kept_box[((size_t)b*TOTK + flat)*4];
            b0 = bb[0]; b1 = bb[1]; b2 = bb[2]; b3 = bb[3];
        }
        out_sc[(size_t)b*KMAX + k] = s;
        out_cl[(size_t)b*KMAX + k] = cl;
        float* ob = &out_box[((size_t)b*KMAX + k)*4];
        ob[0]=b0; ob[1]=b1; ob[2]=b2; ob[3]=b3;
    }
    if (tid == 0){
        out_num[b] = (float)min(fcnt, KMAX);
        g_done[b] = 0;              // reset for next graph replay
    }
}

// ---------------- launch ----------------
extern "C" void kernel_launch(void* const* d_in, const int* in_sizes, int n_in,
                              void* d_out, int out_size){
    const float* cls0 = (const float*)d_in[0];
    const float* bb0  = (const float*)d_in[1];
    const float* obj0 = (const float*)d_in[2];
    const float* cls1 = (const float*)d_in[3];
    const float* bb1  = (const float*)d_in[4];
    const float* obj1 = (const float*)d_in[5];
    const float* cls2 = (const float*)d_in[6];
    const float* bb2  = (const float*)d_in[7];
    const float* obj2 = (const float*)d_in[8];
    float* out = (float*)d_out;

    size_t smem = (size_t)CAP2*8 + (size_t)CAP*8 + (size_t)PFN*16;  // 30,720 B
    k_all<<<BATCH*NC, NTH, smem>>>(cls0, bb0, obj0, cls1, bb1, obj1,
                                   cls2, bb2, obj2, out);
}

// round 8
// speedup vs baseline: 1.1870x; 1.1870x over previous
#include <cuda_runtime.h>
#include <math.h>

#define BATCH 8
#define NC 80
#define NA 8400
#define NA0 6400
#define NA1 1600
#define NA2 400
#define PRE_TOPK 5000
#define KMAX 100
#define TOTK (NC*KMAX)
#define SCORE_THR 0.01f
#define IOU_THR 0.65f
#define NTH 256
#define CAP 512
#define TSEL 160
#define FSORT 256
#define PFN 128
#define PADKEY 0xFFFFFFFFFFFFFFFFull
#define FULLM 0xFFFFFFFFu
#define QBASE 0x3F800000u
typedef unsigned long long u64;

// ---------------- scratch ----------------
__device__ float g_kept_score[BATCH*TOTK];
__device__ float g_kept_box  [BATCH*TOTK*4];
__device__ int   g_done[BATCH];          // zero-init; self-resetting per replay

// decision-exact IoU>thr; IEEE div only in tiny ambiguity band
__device__ __forceinline__ bool iou_sup(float SX1,float SY1,float SX2,float SY2,float SAR,
                                        float x1,float y1,float x2,float y2,float ar){
    float tlx = fmaxf(SX1, x1), tly = fmaxf(SY1, y1);
    float brx = fminf(SX2, x2), bry = fminf(SY2, y2);
    float ww = fmaxf(brx - tlx, 0.f), hh = fmaxf(bry - tly, 0.f);
    float inter = ww*hh;
    float denom = SAR + ar - inter + 1e-6f;
    float d = inter - IOU_THR*denom;
    if (fabsf(d) > 1e-4f*denom) return d > 0.f;
    return __fdiv_rn(inter, denom) > IOU_THR;
}

// monotone cheap approx of 1+e^{-x} (selection surrogate only)
__device__ __forceinline__ float qapprox(float x){
    float t = fminf(fmaxf(-x, -80.f), 80.f);
    int bits = (int)(12102203.0f*t + 1064986316.0f);
    return 1.0f + __int_as_float(bits);
}

// warp-aggregated append (final phase)
__device__ __forceinline__ void wappend(u64* buf, int* cnt, bool pred, u64 val, int bound){
    unsigned pm = __ballot_sync(FULLM, pred);
    if (!pm) return;
    int lane = (int)(threadIdx.x & 31);
    int ldr  = __ffs(pm) - 1;
    int base = 0;
    if (lane == ldr) base = atomicAdd(cnt, __popc(pm));
    base = __shfl_sync(FULLM, base, ldr);
    if (pred){
        int p = base + __popc(pm & ((1u<<lane)-1u));
        if (p < bound) buf[p] = val;
    }
}

// exact box decode (identical arithmetic to all passing rounds)
__device__ __forceinline__ float4 decode_box(int a, int b,
        const float* __restrict__ bb0, const float* __restrict__ bb1,
        const float* __restrict__ bb2){
    float p0,p1,p2,p3,px,py,st;
    if (a < NA0){ int hw=a; const float* p=bb0+(size_t)b*4*NA0;
        p0=p[hw];p1=p[NA0+hw];p2=p[2*NA0+hw];p3=p[3*NA0+hw];
        px=(float)(hw%80)*8.f; py=(float)(hw/80)*8.f; st=8.f;
    } else if (a < NA0+NA1){ int hw=a-NA0; const float* p=bb1+(size_t)b*4*NA1;
        p0=p[hw];p1=p[NA1+hw];p2=p[2*NA1+hw];p3=p[3*NA1+hw];
        px=(float)(hw%40)*16.f; py=(float)(hw/40)*16.f; st=16.f;
    } else { int hw=a-NA0-NA1; const float* p=bb2+(size_t)b*4*NA2;
        p0=p[hw];p1=p[NA2+hw];p2=p[2*NA2+hw];p3=p[3*NA2+hw];
        px=(float)(hw%20)*32.f; py=(float)(hw/20)*32.f; st=32.f;
    }
    float cx=p0*st+px, cy=p1*st+py, w=expf(p2)*st, h=expf(p3)*st;
    return make_float4(cx-w*0.5f, cy-h*0.5f, cx+w*0.5f, cy+h*0.5f);
}

__device__ __forceinline__ float cls_at(int a, const float* c0, const float* c1, const float* c2){
    if (a < NA0) return c0[a];
    if (a < NA0+NA1) return c1[a-NA0];
    return c2[a-NA0-NA1];
}
__device__ __forceinline__ float obj_at(int a, const float* o0, const float* o1, const float* o2){
    if (a < NA0) return o0[a];
    if (a < NA0+NA1) return o1[a-NA0];
    return o2[a-NA0-NA1];
}

// ---------------- the fused kernel ----------------
__global__ __launch_bounds__(NTH, 5) void k_all(
    const float* __restrict__ cls0, const float* __restrict__ bb0, const float* __restrict__ obj0,
    const float* __restrict__ cls1, const float* __restrict__ bb1, const float* __restrict__ obj1,
    const float* __restrict__ cls2, const float* __restrict__ bb2, const float* __restrict__ obj2,
    float* __restrict__ out){

    extern __shared__ char smraw[];
    unsigned* sc = (unsigned*)smraw;                             // NA surrogate q-bits
    u64* bk      = (u64*)(smraw + (size_t)NA*4);                 // CAP batch keys (also final fkey)
    float4* pbox = (float4*)(smraw + (size_t)NA*4 + (size_t)CAP*8); // PFN decoded boxes

    __shared__ float kx1[KMAX], ky1[KMAX], kx2[KMAX], ky2[KMAX], ksc[KMAX], kar[KMAX];
    __shared__ unsigned hist[256];
    __shared__ float cbx1[32], cby1[32], cbx2[32], cby2[32], cbar[32], cbs[32];
    __shared__ unsigned conf[32];
    __shared__ int sup[32];
    __shared__ unsigned s_Tbits, s_vmask, s_pref;
    __shared__ int s_total, s_selbin, s_cumlo, s_cumhi, s_sub, s_subPe, s_subPi;
    __shared__ int s_cnt, s_kept, s_rank, s_last, s_kkv;

    int tid = threadIdx.x;
    int lane = tid & 31, w = tid >> 5;
    int bc = blockIdx.x;
    int b = bc / NC, c = bc % NC;

    const float* c0 = cls0 + ((size_t)b*NC + c)*NA0;
    const float* c1 = cls1 + ((size_t)b*NC + c)*NA1;
    const float* c2 = cls2 + ((size_t)b*NC + c)*NA2;
    const float* o0 = obj0 + (size_t)b*NA0;
    const float* o1 = obj1 + (size_t)b*NA1;
    const float* o2 = obj2 + (size_t)b*NA2;

    const unsigned QHI = __float_as_uint(110.0f);   // surrogate ~score>0.009 band

    // ---- phase 1: compute surrogate q-bits, store to smem, fused 214-bin histogram
    hist[tid] = 0;
    if (tid == 0){ s_kept = 0; s_rank = 0; }
    __syncthreads();
    {
        const float4* c0v = (const float4*)c0;
        const float4* c1v = (const float4*)c1;
        const float4* c2v = (const float4*)c2;
        const float4* o0v = (const float4*)o0;
        const float4* o1v = (const float4*)o1;
        const float4* o2v = (const float4*)o2;
        uint4* scv = (uint4*)sc;
        const int NQ = (2100 + NTH - 1)/NTH;    // 9
        for (int it = 0; it < NQ; it++){
            int i = it*NTH + tid;
            if (i < 2100){
                float4 cv, ov;
                if (i < 1600){ cv = c0v[i]; ov = o0v[i]; }
                else if (i < 2000){ cv = c1v[i-1600]; ov = o1v[i-1600]; }
                else { cv = c2v[i-2000]; ov = o2v[i-2000]; }
                uint4 o;
                o.x = __float_as_uint(qapprox(cv.x)*qapprox(ov.x));
                o.y = __float_as_uint(qapprox(cv.y)*qapprox(ov.y));
                o.z = __float_as_uint(qapprox(cv.z)*qapprox(ov.z));
                o.w = __float_as_uint(qapprox(cv.w)*qapprox(ov.w));
                scv[i] = o;
                if (o.x < QHI) atomicAdd(&hist[(o.x-QBASE)>>18], 1u);
                if (o.y < QHI) atomicAdd(&hist[(o.y-QBASE)>>18], 1u);
                if (o.z < QHI) atomicAdd(&hist[(o.z-QBASE)>>18], 1u);
                if (o.w < QHI) atomicAdd(&hist[(o.w-QBASE)>>18], 1u);
            }
        }
    }
    __syncthreads();

    unsigned prevT = 0;
    bool haveHist = true, done = false;
    const uint2* sc2 = (const uint2*)sc;
    const int NH2 = (NA/2 + NTH - 1)/NTH;   // 17

    while (!done){
        if (!haveHist){
            hist[tid] = 0; __syncthreads();
            for (int it = 0; it < NH2; it++){
                int i = it*NTH + tid;
                if (i < NA/2){
                    uint2 v = sc2[i];
                    if (v.x < QHI && v.x > prevT) atomicAdd(&hist[(v.x-QBASE)>>18], 1u);
                    if (v.y < QHI && v.y > prevT) atomicAdd(&hist[(v.y-QBASE)>>18], 1u);
                }
            }
            __syncthreads();
        }
        // ---- select threshold bin (warp 0) ----
        if (tid < 32){
            unsigned cc[8]; unsigned sum = 0;
            #pragma unroll
            for (int j = 0; j < 8; j++){ cc[j] = hist[lane*8+j]; sum += cc[j]; }
            unsigned incl = sum;
            #pragma unroll
            for (int off = 1; off < 32; off <<= 1){
                unsigned n = __shfl_up_sync(FULLM, incl, off);
                if (lane >= off) incl += n;
            }
            unsigned excl = incl - sum;
            unsigned total = __shfl_sync(FULLM, incl, 31);
            if (lane == 0) s_total = (int)total;
            if (total > CAP && (int)excl < TSEL && TSEL <= (int)incl){
                unsigned run = excl;
                #pragma unroll
                for (int j = 0; j < 8; j++){
                    if ((int)(run + cc[j]) >= TSEL){
                        s_selbin = lane*8+j; s_cumlo = (int)run; s_cumhi = (int)(run+cc[j]);
                        break;
                    }
                    run += cc[j];
                }
            }
        }
        __syncthreads();
        int total = s_total;
        if (total == 0) break;
        bool takeall = (total <= CAP);

        if (takeall){
            if (tid == 0) s_Tbits = QHI - 1u;
        } else if (s_cumhi <= CAP){
            if (tid == 0) s_Tbits = QBASE + (((unsigned)s_selbin+1u)<<18) - 1u;
        } else {
            // refine within straddling bin on bits>>10 (rare)
            int selbin = s_selbin;
            __syncthreads();
            hist[tid] = 0; __syncthreads();
            for (int it = 0; it < NH2; it++){
                int i = it*NTH + tid;
                if (i < NA/2){
                    uint2 v = sc2[i];
                    if (v.x < QHI && v.x > prevT && (int)((v.x-QBASE)>>18) == selbin)
                        atomicAdd(&hist[(v.x>>10)&255], 1u);
                    if (v.y < QHI && v.y > prevT && (int)((v.y-QBASE)>>18) == selbin)
                        atomicAdd(&hist[(v.y>>10)&255], 1u);
                }
            }
            __syncthreads();
            if (tid < 32){
                int target2 = TSEL - s_cumlo;
                unsigned cc[8]; unsigned sum = 0;
                #pragma unroll
                for (int j = 0; j < 8; j++){ cc[j] = hist[lane*8+j]; sum += cc[j]; }
                unsigned incl = sum;
                #pragma unroll
                for (int off = 1; off < 32; off <<= 1){
                    unsigned n = __shfl_up_sync(FULLM, incl, off);
                    if (lane >= off) incl += n;
                }
                unsigned excl = incl - sum;
                if ((int)excl < target2 && target2 <= (int)incl){
                    unsigned run = excl;
                    #pragma unroll
                    for (int j = 0; j < 8; j++){
                        if ((int)(run + cc[j]) >= target2){
                            s_sub = lane*8+j; s_subPe = (int)run; s_subPi = (int)(run+cc[j]);
                            break;
                        }
                        run += cc[j];
                    }
                }
            }
            __syncthreads();
            if (tid == 0){
                int sub = s_sub;
                if (s_cumlo + s_subPi > CAP && s_subPe > 0) sub -= 1;
                s_Tbits = QBASE + (((unsigned)selbin)<<18) + (((unsigned)sub+1u)<<10) - 1u;
            }
        }
        __syncthreads();
        unsigned Tbits = s_Tbits;

        // ---- compact candidate indices ----
        if (tid == 0) s_cnt = 0;
        __syncthreads();
        for (int it = 0; it < NH2; it++){
            int i = it*NTH + tid;
            if (i < NA/2){
                uint2 v = sc2[i];
                if (v.x > prevT && v.x <= Tbits){
                    int p = atomicAdd(&s_cnt, 1);
                    if (p < CAP) bk[p] = (u64)(unsigned)(2*i);
                }
                if (v.y > prevT && v.y <= Tbits){
                    int p = atomicAdd(&s_cnt, 1);
                    if (p < CAP) bk[p] = (u64)(unsigned)(2*i+1);
                }
            }
        }
        __syncthreads();
        int cnt = min(s_cnt, CAP);
        int sortN = (cnt <= 256) ? 256 : 512;

        // ---- exact rescore (bit-identical to reference path) ----
        for (int p = tid; p < sortN; p += NTH){
            if (p < cnt){
                int a = (int)(unsigned)bk[p];
                float cv = cls_at(a, c0, c1, c2);
                float ov = obj_at(a, o0, o1, o2);
                float s = (1.0f/(1.0f+expf(-cv))) * (1.0f/(1.0f+expf(-ov)));
                bk[p] = (s > SCORE_THR)
                    ? (((u64)(~__float_as_uint(s)) << 32) | (unsigned)a)
                    : PADKEY;
            } else bk[p] = PADKEY;
        }
        __syncthreads();

        // ---- bitonic sort: score desc, ties lower index first ----
        for (int ksz = 2; ksz <= sortN; ksz <<= 1){
            for (int j = ksz >> 1; j > 0; j >>= 1){
                for (int idx = tid; idx < sortN; idx += NTH){
                    int l = idx ^ j;
                    if (l > idx){
                        u64 a0 = bk[idx], a1 = bk[l];
                        bool up = ((idx & ksz) == 0);
                        if ((a0 > a1) == up){ bk[idx] = a1; bk[l] = a0; }
                    }
                }
                __syncthreads();
            }
        }

        // ---- decode boxes for first PFN sorted candidates ----
        int pn = min(cnt, PFN);
        for (int p = tid; p < pn; p += NTH){
            u64 k2 = bk[p];
            if (k2 != PADKEY)
                pbox[p] = decode_box((int)(unsigned)(k2 & 0xFFFFFFFFull), b, bb0, bb1, bb2);
        }
        __syncthreads();

        // ---- greedy NMS over chunks of 32 sorted candidates ----
        int t0 = 0;
        while (t0 < cnt){
            int K = s_kept, rank = s_rank;
            if (K >= KMAX || rank >= PRE_TOPK) break;
            int chunk_n = min(32, min(cnt - t0, PRE_TOPK - rank));

            if (tid < 32){
                bool lv = lane < chunk_n;
                u64 k2 = lv ? bk[t0+lane] : PADKEY;
                bool cvalid = lv && (k2 != PADKEY);
                float4 bb = make_float4(0.f,0.f,0.f,0.f);
                float sval = 0.f;
                if (cvalid){
                    int t = t0 + lane;
                    int a = (int)(unsigned)(k2 & 0xFFFFFFFFull);
                    sval = __uint_as_float(~(unsigned)(k2>>32));
                    bb = (t < pn) ? pbox[t] : decode_box(a, b, bb0, bb1, bb2);
                }
                cbx1[lane]=bb.x; cby1[lane]=bb.y; cbx2[lane]=bb.z; cby2[lane]=bb.w;
                cbar[lane]=(bb.z-bb.x)*(bb.w-bb.y); cbs[lane]=sval;
                conf[lane]=0; sup[lane]=0;
                unsigned vm = __ballot_sync(FULLM, cvalid);
                if (lane == 0) s_vmask = vm;
            }
            __syncthreads();
            unsigned vm = s_vmask;

            {   // all 8 warps: kept-suppression + intra-chunk conflict matrix
                int i = lane;
                if ((vm>>i)&1u){
                    float x1=cbx1[i], y1=cby1[i], x2=cbx2[i], y2=cby2[i], ar=cbar[i];
                    bool s = false;
                    for (int m = w; m < K; m += 8)
                        s |= iou_sup(kx1[m],ky1[m],kx2[m],ky2[m],kar[m], x1,y1,x2,y2,ar);
                    if (s) sup[i] = 1;
                    unsigned cf = 0;
                    for (int j = w; j < i; j += 8){
                        if ((vm>>j)&1u){
                            if (iou_sup(cbx1[j],cby1[j],cbx2[j],cby2[j],cbar[j],
                                        x1,y1,x2,y2,ar)) cf |= 1u<<j;
                        }
                    }
                    if (cf) atomicOr(&conf[i], cf);
                }
            }
            __syncthreads();

            if (tid < 32){
                bool base_ok = ((vm>>lane)&1u) && (sup[lane] == 0);
                unsigned myconf = conf[lane];
                unsigned undecided = __ballot_sync(FULLM, base_ok);
                unsigned kept_mask = 0;
                while (undecided){
                    bool und = (undecided >> lane) & 1u;
                    bool decidable = und && ((myconf & undecided & ~(1u<<lane)) == 0);
                    bool keepme = decidable && ((myconf & kept_mask) == 0);
                    unsigned dec = __ballot_sync(FULLM, decidable);
                    unsigned kp  = __ballot_sync(FULLM, keepme);
                    kept_mask |= kp;
                    undecided &= ~dec;
                }
                int pos = K + __popc(kept_mask & ((1u<<lane)-1u));
                if (((kept_mask>>lane)&1u) && pos < KMAX){
                    kx1[pos]=cbx1[lane]; ky1[pos]=cby1[lane];
                    kx2[pos]=cbx2[lane]; ky2[pos]=cby2[lane];
                    kar[pos]=cbar[lane]; ksc[pos]=cbs[lane];
                }
                if (lane == 0){
                    s_kept = min(K + __popc(kept_mask), KMAX);
                    s_rank = rank + __popc(vm);
                }
            }
            __syncthreads();
            t0 += 32;
        }

        if (s_kept >= KMAX || s_rank >= PRE_TOPK || takeall) done = true;
        else { prevT = Tbits; haveHist = false; }
        __syncthreads();
    }

    // ---- per-class outputs ----
    int kept = s_kept;
    float* keptS = g_kept_score + (size_t)bc*KMAX;
    float* keptB = g_kept_box   + (size_t)bc*KMAX*4;
    for (int j = tid; j < KMAX; j += NTH){
        if (j < kept){
            keptS[j] = ksc[j];
            keptB[j*4+0]=kx1[j]; keptB[j*4+1]=ky1[j];
            keptB[j*4+2]=kx2[j]; keptB[j*4+3]=ky2[j];
        } else {
            keptS[j] = -1.f;
            keptB[j*4+0]=0.f; keptB[j*4+1]=0.f; keptB[j*4+2]=0.f; keptB[j*4+3]=0.f;
        }
    }

    // ---- last CTA of this image runs the global top-100 ----
    __threadfence();
    __syncthreads();
    if (tid == 0){
        int r = atomicAdd(&g_done[b], 1);
        s_last = (r == NC - 1) ? 1 : 0;
    }
    __syncthreads();
    if (!s_last) return;
    __threadfence();

    u64* fkey = bk;   // alias: batch buffer is free now
    const float* ks = g_kept_score + (size_t)b*TOTK;
    const int NJ = (TOTK + NTH - 1)/NTH;

    unsigned prefix = 0; int kk = KMAX;
    for (int shift = 24; shift >= 0; shift -= 8){
        unsigned mask = (shift == 24) ? 0u : (0xFFFFFFFFu << (shift+8));
        hist[tid] = 0; __syncthreads();
        for (int it = 0; it < NJ; it++){
            int j = it*NTH + tid;
            if (j < TOTK){
                unsigned u = __float_as_uint(ks[j]);
                unsigned v = (u & 0x80000000u) ? ~u : (u | 0x80000000u);
                if ((v & mask) == prefix) atomicAdd(&hist[(v>>shift)&255], 1u);
            }
        }
        __syncthreads();
        if (tid < 32){
            unsigned cc[8]; unsigned sum = 0;
            #pragma unroll
            for (int q = 0; q < 8; q++){ cc[q] = hist[lane*8+q]; sum += cc[q]; }
            unsigned incl = sum;
            #pragma unroll
            for (int off = 1; off < 32; off <<= 1){
                unsigned n = __shfl_down_sync(FULLM, incl, off);
                if (lane + off < 32) incl += n;
            }
            unsigned below = incl - sum;
            if ((int)below < kk && kk <= (int)incl){
                unsigned run = below;
                for (int q = 7; q >= 0; q--){
                    if (run + cc[q] >= (unsigned)kk){
                        s_pref = prefix | (((unsigned)(lane*8+q)) << shift);
                        s_kkv  = kk - (int)run;
                        break;
                    }
                    run += cc[q];
                }
            }
        }
        __syncthreads();
        prefix = s_pref; kk = s_kkv;
        __syncthreads();
    }
    unsigned T = prefix;
    const unsigned MAP0 = 0x80000000u;

    if (tid == 0) s_cnt = 0;
    __syncthreads();
    for (int it = 0; it < NJ; it++){
        int j = it*NTH + tid;
        bool inb = j < TOTK;
        unsigned v = 0;
        if (inb){
            unsigned u = __float_as_uint(ks[j]);
            v = (u & 0x80000000u) ? ~u : (u | 0x80000000u);
        }
        wappend(fkey, &s_cnt, inb && v >= T && v > MAP0,
                ((u64)v << 32) | (0xFFFFFFFFu - (unsigned)j), FSORT);
    }
    __syncthreads();
    int fcnt = min(s_cnt, FSORT);
    for (int p = fcnt + tid; p < FSORT; p += NTH) fkey[p] = 0ull;
    __syncthreads();

    for (int ksz = 2; ksz <= FSORT; ksz <<= 1){
        for (int j = ksz >> 1; j > 0; j >>= 1){
            if (tid < FSORT){
                int idx = tid, l = idx ^ j;
                if (l > idx){
                    u64 a0 = fkey[idx], a1 = fkey[l];
                    bool up = ((idx & ksz) == 0);
                    if ((a0 > a1) == up){ fkey[idx] = a1; fkey[l] = a0; }
                }
            }
            __syncthreads();
        }
    }

    float* out_num = out;
    float* out_box = out + BATCH;
    float* out_sc  = out + BATCH + (size_t)BATCH*KMAX*4;
    float* out_cl  = out + BATCH + (size_t)BATCH*KMAX*4 + (size_t)BATCH*KMAX;

    for (int k = tid; k < KMAX; k += NTH){
        bool valid = (k < fcnt);
        float s = 0.f, cl = -1.f, b0=0.f, b1=0.f, b2=0.f, b3=0.f;
        if (valid){
            u64 k2 = fkey[FSORT-1-k];
            int flat = (int)(0xFFFFFFFFu - (unsigned)(k2 & 0xFFFFFFFFull));
            s  = g_kept_score[(size_t)b*TOTK + flat];
            cl = (float)(flat / KMAX);
            const float* bb = &g_kept_box[((size_t)b*TOTK + flat)*4];
            b0 = bb[0]; b1 = bb[1]; b2 = bb[2]; b3 = bb[3];
        }
        out_sc[(size_t)b*KMAX + k] = s;
        out_cl[(size_t)b*KMAX + k] = cl;
        float* ob = &out_box[((size_t)b*KMAX + k)*4];
        ob[0]=b0; ob[1]=b1; ob[2]=b2; ob[3]=b3;
    }
    if (tid == 0){
        out_num[b] = (float)min(fcnt, KMAX);
        g_done[b] = 0;              // reset for next graph replay
    }
}

// ---------------- launch ----------------
extern "C" void kernel_launch(void* const* d_in, const int* in_sizes, int n_in,
                              void* d_out, int out_size){
    const float* cls0 = (const float*)d_in[0];
    const float* bb0  = (const float*)d_in[1];
    const float* obj0 = (const float*)d_in[2];
    const float* cls1 = (const float*)d_in[3];
    const float* bb1  = (const float*)d_in[4];
    const float* obj1 = (const float*)d_in[5];
    const float* cls2 = (const float*)d_in[6];
    const float* bb2  = (const float*)d_in[7];
    const float* obj2 = (const float*)d_in[8];
    float* out = (float*)d_out;

    size_t smem = (size_t)NA*4 + (size_t)CAP*8 + (size_t)PFN*16;  // 39,744 B
    k_all<<<BATCH*NC, NTH, smem>>>(cls0, bb0, obj0, cls1, bb1, obj1,
                                   cls2, bb2, obj2, out);
}